// round 6
// baseline (speedup 1.0000x reference)
#include <cuda_runtime.h>
#include <cuda_bf16.h>
#include <cstdint>

#define B_  32
#define C_  32
#define H_  160
#define W_  160
#define TH  20
#define TW  20
#define NT  64
#define EPS 1e-5f
#define HW  (H_ * W_)        // 25600

// Padded h tile: 22 rows x 24 cols = 528 pixel-rows, each 128B (32ch hi bf16 | 32ch lo bf16)
#define H_BYTES (528 * 128)            // 67584
#define W_BYTES (9 * 32 * 128)         // 36864 (rows = tap*32+ic, [hi oc0-31 | lo oc0-31])
#define SMEM_REQ (1024 + H_BYTES + W_BYTES)

__device__ float d_scale[NT * C_];
__device__ float d_shift[NT * C_];
// Pre-split, pre-swizzled weights: row = tap*32+ic, col bytes = [hi oc*2 | 64 + lo oc*2]
__device__ __align__(16) __nv_bfloat16 g_w2[NT][288 * 64];

__device__ __forceinline__ uint32_t sw128(uint32_t o) { return o ^ ((o >> 3) & 0x70u); }

__device__ __forceinline__ uint32_t smem_u32(const void* p) {
    uint32_t a;
    asm("{ .reg .u64 t; cvta.to.shared.u64 t, %1; cvt.u32.u64 %0, t; }" : "=r"(a) : "l"(p));
    return a;
}

__device__ __forceinline__ void ldm_x4(uint32_t addr,
                                       uint32_t& r0, uint32_t& r1,
                                       uint32_t& r2, uint32_t& r3) {
    asm volatile("ldmatrix.sync.aligned.m8n8.x4.shared.b16 {%0,%1,%2,%3}, [%4];"
                 : "=r"(r0), "=r"(r1), "=r"(r2), "=r"(r3) : "r"(addr));
}
__device__ __forceinline__ void ldm_x4_t(uint32_t addr,
                                         uint32_t& r0, uint32_t& r1,
                                         uint32_t& r2, uint32_t& r3) {
    asm volatile("ldmatrix.sync.aligned.m8n8.x4.trans.shared.b16 {%0,%1,%2,%3}, [%4];"
                 : "=r"(r0), "=r"(r1), "=r"(r2), "=r"(r3) : "r"(addr));
}
__device__ __forceinline__ void mma16816(float* d, uint32_t a0, uint32_t a1,
                                         uint32_t a2, uint32_t a3,
                                         uint32_t b0, uint32_t b1) {
    asm volatile(
        "mma.sync.aligned.m16n8k16.row.col.f32.bf16.bf16.f32 "
        "{%0,%1,%2,%3},{%4,%5,%6,%7},{%8,%9},{%0,%1,%2,%3};"
        : "+f"(d[0]), "+f"(d[1]), "+f"(d[2]), "+f"(d[3])
        : "r"(a0), "r"(a1), "r"(a2), "r"(a3), "r"(b0), "r"(b1));
}

// ---------------------------------------------------------------------------
// Kernel 1: BN stats per (tile, channel=oc) + weight hi/lo split into g_w2.
// ---------------------------------------------------------------------------
__global__ __launch_bounds__(256) void bn_stats_kernel(
    const float* __restrict__ x,
    const float* __restrict__ gamma,
    const float* __restrict__ beta,
    const float* __restrict__ conv_w)
{
    const int bid = blockIdx.x;           // t*32 + c
    const int t = bid >> 5;
    const int c = bid & 31;
    const int ti = t >> 3, tj = t & 7;

    const float* base = x + (size_t)c * HW + (size_t)(ti * TH) * W_ + tj * TW;
    const size_t bstride = (size_t)C_ * HW;

    float s = 0.f, s2 = 0.f;
    for (int i = threadIdx.x; i < B_ * TH * 5; i += 256) {
        int b = i / (TH * 5);
        int r = i - b * (TH * 5);
        int y = r / 5, xq = r - y * 5;
        float4 v = *reinterpret_cast<const float4*>(
            &base[(size_t)b * bstride + y * W_ + xq * 4]);
        s  += (v.x + v.y) + (v.z + v.w);
        s2 += (v.x * v.x + v.y * v.y) + (v.z * v.z + v.w * v.w);
    }

    // weight split for oc = c: rows = tap*32 + ic, col = oc
    for (int i = threadIdx.x; i < 288; i += 256) {
        int ic = i / 9, tap = i - ic * 9;
        float w = conv_w[(((size_t)t * C_ + c) * C_ + ic) * 9 + tap];
        __nv_bfloat16 hi = __float2bfloat16(w);
        __nv_bfloat16 lo = __float2bfloat16(w - __bfloat162float(hi));
        uint32_t row = (uint32_t)(tap * 32 + ic);
        g_w2[t][sw128(row * 128 + c * 2) >> 1]      = hi;
        g_w2[t][sw128(row * 128 + 64 + c * 2) >> 1] = lo;
    }

    __shared__ float ss[256], ss2[256];
    ss[threadIdx.x] = s;
    ss2[threadIdx.x] = s2;
    __syncthreads();
    for (int off = 128; off > 0; off >>= 1) {
        if (threadIdx.x < off) {
            ss[threadIdx.x]  += ss[threadIdx.x + off];
            ss2[threadIdx.x] += ss2[threadIdx.x + off];
        }
        __syncthreads();
    }
    if (threadIdx.x == 0) {
        const float invN = 1.f / (float)(B_ * TH * TW);
        float mean = ss[0] * invN;
        float var  = ss2[0] * invN - mean * mean;
        float sc = gamma[bid] * rsqrtf(var + EPS);
        d_scale[bid] = sc;
        d_shift[bid] = beta[bid] - mean * sc;
    }
}

// ---------------------------------------------------------------------------
// Kernel 2: per-(tile, batch) implicit-GEMM 3x3 conv via mma.sync bf16 hi/lo.
// B fragments hoisted across each warp's m-tiles (multi-tile accumulators).
// ---------------------------------------------------------------------------
__global__ __launch_bounds__(256, 2) void conv_kernel(
    const float* __restrict__ x,
    const float* __restrict__ conv_b,
    float* __restrict__ out)
{
    extern __shared__ char smem[];
    const uint32_t sbase = smem_u32(smem);
    const uint32_t hb = (sbase + 1023u) & ~1023u;
    const uint32_t wb = hb + H_BYTES;
    char* hptr = smem + (hb - sbase);
    char* wptr = smem + (wb - sbase);

    const int bid = blockIdx.x;     // t*32 + b
    const int t = bid >> 5;
    const int b = bid & 31;
    const int ti = t >> 3, tj = t & 7;
    const int tid = threadIdx.x;
    const int warp = tid >> 5;
    const int lane = tid & 31;

    // ---- zero h region (padding must be 0) ----
    {
        uint4 z = make_uint4(0, 0, 0, 0);
        uint4* hz = reinterpret_cast<uint4*>(hptr);
        for (int i = tid; i < H_BYTES / 16; i += 256) hz[i] = z;
    }

    // ---- copy pre-split weights (already in swizzled layout) ----
    {
        const uint4* gsrc = reinterpret_cast<const uint4*>(g_w2[t]);
        uint4* wdst = reinterpret_cast<uint4*>(wptr);
        for (int i = tid; i < W_BYTES / 16; i += 256) wdst[i] = gsrc[i];
    }
    __syncthreads();

    // ---- load x tile, BN+ReLU, split to bf16 hi/lo, store swizzled ----
    const size_t xtile = ((size_t)b * C_) * HW + (size_t)(ti * TH) * W_ + tj * TW;
    for (int i = tid; i < C_ * TH * 5; i += 256) {
        int c = i / 100;
        int rr = i - c * 100;
        int y = rr / 5, xq = rr - y * 5;
        float4 v = *reinterpret_cast<const float4*>(
            &x[xtile + (size_t)c * HW + y * W_ + xq * 4]);
        float sc = d_scale[t * C_ + c];
        float sh = d_shift[t * C_ + c];
        int row0 = (y + 1) * 24 + xq * 4 + 1;
        float vv[4] = {v.x, v.y, v.z, v.w};
#pragma unroll
        for (int k = 0; k < 4; k++) {
            float f = fmaxf(fmaf(vv[k], sc, sh), 0.f);
            __nv_bfloat16 hi = __float2bfloat16(f);
            __nv_bfloat16 lo = __float2bfloat16(f - __bfloat162float(hi));
            uint32_t off = (uint32_t)(row0 + k) * 128 + c * 2;
            *reinterpret_cast<__nv_bfloat16*>(hptr + sw128(off))      = hi;
            *reinterpret_cast<__nv_bfloat16*>(hptr + sw128(off + 64)) = lo;
        }
    }
    __syncthreads();

    // ---- warp-level implicit GEMM: warp owns tiles {warp, warp+8, warp+16, [24]} ----
    const int li   = lane & 7;
    const int sel8 = (lane >> 3) & 1;
    const int selk = (lane >> 4) & 1;
    const int tg   = lane & 3;
    const int g    = lane >> 2;

    const int ntiles = (warp == 0) ? 4 : 3;

    // per-tile lane A-row base (padded coords)
    int pr0[4];
#pragma unroll
    for (int tt = 0; tt < 4; tt++) {
        int mt = (tt == 3) ? 24 : (warp + tt * 8);
        int m = mt * 16 + li + sel8 * 8;
        int my = m / 20, mx = m - my * 20;
        pr0[tt] = my * 24 + mx;
    }

    float acc[4][4][4];   // [tile][j(oc-oct)][frag]
#pragma unroll
    for (int tt = 0; tt < 4; tt++)
#pragma unroll
        for (int j = 0; j < 4; j++)
#pragma unroll
            for (int k = 0; k < 4; k++) acc[tt][j][k] = 0.f;

#pragma unroll 1
    for (int tap = 0; tap < 9; tap++) {
        const int dyx = (tap / 3) * 24 + (tap % 3);
        const uint32_t brow = wb + (uint32_t)(tap * 32 + li + sel8 * 8) * 128;
#pragma unroll
        for (int kc = 0; kc < 2; kc++) {
            // ---- B fragments: load ONCE per (tap,kc), reuse across all tiles ----
            const uint32_t bro = brow + (uint32_t)(kc * 16) * 128;
            const uint32_t sb0 = (uint32_t)selk;          // n 0-15
            const uint32_t sb1 = (uint32_t)(2 + selk);    // n 16-31
            uint32_t bh[8], bl[8];
            ldm_x4_t(bro + ((sb0 ^ (uint32_t)li) << 4),       bh[0], bh[1], bh[2], bh[3]);
            ldm_x4_t(bro + ((sb1 ^ (uint32_t)li) << 4),       bh[4], bh[5], bh[6], bh[7]);
            ldm_x4_t(bro + (((sb0 + 4) ^ (uint32_t)li) << 4), bl[0], bl[1], bl[2], bl[3]);
            ldm_x4_t(bro + (((sb1 + 4) ^ (uint32_t)li) << 4), bl[4], bl[5], bl[6], bl[7]);

            const uint32_t sa = (uint32_t)(kc * 2 + selk);
#pragma unroll
            for (int tt = 0; tt < 4; tt++) {
                if (tt >= ntiles) break;
                const int inrow = pr0[tt] + dyx;
                const uint32_t arow = hb + (uint32_t)inrow * 128;
                const uint32_t rx = (uint32_t)(inrow & 7);
                uint32_t ah0, ah1, ah2, ah3, al0, al1, al2, al3;
                ldm_x4(arow + ((sa ^ rx) << 4),        ah0, ah1, ah2, ah3);
                ldm_x4(arow + (((sa + 4) ^ rx) << 4),  al0, al1, al2, al3);
#pragma unroll
                for (int j = 0; j < 4; j++) {
                    mma16816(acc[tt][j], ah0, ah1, ah2, ah3, bh[2 * j], bh[2 * j + 1]);
                    mma16816(acc[tt][j], ah0, ah1, ah2, ah3, bl[2 * j], bl[2 * j + 1]);
                    mma16816(acc[tt][j], al0, al1, al2, al3, bh[2 * j], bh[2 * j + 1]);
                }
            }
        }
    }

    // ---- epilogue: + bias + residual, direct from fragments ----
    float cb0[4], cb1[4];
#pragma unroll
    for (int j = 0; j < 4; j++) {
        cb0[j] = conv_b[t * C_ + j * 8 + 2 * tg];
        cb1[j] = conv_b[t * C_ + j * 8 + 2 * tg + 1];
    }

    const size_t bb = (size_t)b * C_ * HW;
    const int gtile = (ti * TH) * W_ + tj * TW;

#pragma unroll 1
    for (int tt = 0; tt < 4; tt++) {
        if (tt >= ntiles) break;
        const int mt = (tt == 3) ? 24 : (warp + tt * 8);
        const int m0 = mt * 16;
        const int p0 = m0 + g;
        const int p1 = p0 + 8;
        const int y0 = p0 / 20, x0 = p0 - y0 * 20;
        const int y1 = p1 / 20, x1 = p1 - y1 * 20;
        const size_t pa0 = (size_t)(gtile + y0 * W_ + x0);
        const size_t pa1 = (size_t)(gtile + y1 * W_ + x1);
#pragma unroll
        for (int j = 0; j < 4; j++) {
            const int oc = j * 8 + 2 * tg;
            const size_t a00 = bb + (size_t)oc * HW + pa0;
            const size_t a10 = bb + (size_t)oc * HW + pa1;
            out[a00]      = acc[tt][j][0] + cb0[j] + x[a00];
            out[a00 + HW] = acc[tt][j][1] + cb1[j] + x[a00 + HW];
            out[a10]      = acc[tt][j][2] + cb0[j] + x[a10];
            out[a10 + HW] = acc[tt][j][3] + cb1[j] + x[a10 + HW];
        }
    }
}

// ---------------------------------------------------------------------------
extern "C" void kernel_launch(void* const* d_in, const int* in_sizes, int n_in,
                              void* d_out, int out_size)
{
    const float* x      = (const float*)d_in[0];
    const float* gamma  = (const float*)d_in[1];
    const float* beta   = (const float*)d_in[2];
    const float* conv_w = (const float*)d_in[3];
    const float* conv_b = (const float*)d_in[4];
    float* out = (float*)d_out;

    bn_stats_kernel<<<NT * C_, 256>>>(x, gamma, beta, conv_w);

    cudaFuncSetAttribute(conv_kernel,
                         cudaFuncAttributeMaxDynamicSharedMemorySize, SMEM_REQ);
    conv_kernel<<<NT * B_, 256, SMEM_REQ>>>(x, conv_b, out);
}

// round 7
// speedup vs baseline: 1.5339x; 1.5339x over previous
#include <cuda_runtime.h>
#include <cuda_bf16.h>
#include <cstdint>

#define B_  32
#define C_  32
#define H_  160
#define W_  160
#define TH  20
#define TW  20
#define NT  64
#define EPS 1e-5f
#define HW  (H_ * W_)        // 25600

// Padded h tile: 22 rows x 24 cols = 528 pixel-rows, each 128B (32ch hi bf16 | 32ch lo bf16)
#define H_BYTES (528 * 128)            // 67584
#define W_BYTES (9 * 32 * 128)         // 36864 (rows = tap*32+ic, [hi oc0-31 | lo oc0-31])
#define SMEM_REQ (1024 + H_BYTES + W_BYTES)

__device__ float d_scale[NT * C_];
__device__ float d_shift[NT * C_];
// Pre-split, pre-swizzled weights: row = tap*32+ic, col bytes = [hi oc*2 | 64 + lo oc*2]
__device__ __align__(16) __nv_bfloat16 g_w2[NT][288 * 64];

__device__ __forceinline__ uint32_t sw128(uint32_t o) { return o ^ ((o >> 3) & 0x70u); }

__device__ __forceinline__ uint32_t smem_u32(const void* p) {
    uint32_t a;
    asm("{ .reg .u64 t; cvta.to.shared.u64 t, %1; cvt.u32.u64 %0, t; }" : "=r"(a) : "l"(p));
    return a;
}

__device__ __forceinline__ void ldm_x4(uint32_t addr,
                                       uint32_t& r0, uint32_t& r1,
                                       uint32_t& r2, uint32_t& r3) {
    asm volatile("ldmatrix.sync.aligned.m8n8.x4.shared.b16 {%0,%1,%2,%3}, [%4];"
                 : "=r"(r0), "=r"(r1), "=r"(r2), "=r"(r3) : "r"(addr));
}
__device__ __forceinline__ void ldm_x4_t(uint32_t addr,
                                         uint32_t& r0, uint32_t& r1,
                                         uint32_t& r2, uint32_t& r3) {
    asm volatile("ldmatrix.sync.aligned.m8n8.x4.trans.shared.b16 {%0,%1,%2,%3}, [%4];"
                 : "=r"(r0), "=r"(r1), "=r"(r2), "=r"(r3) : "r"(addr));
}
__device__ __forceinline__ void mma16816(float* d, uint32_t a0, uint32_t a1,
                                         uint32_t a2, uint32_t a3,
                                         uint32_t b0, uint32_t b1) {
    asm volatile(
        "mma.sync.aligned.m16n8k16.row.col.f32.bf16.bf16.f32 "
        "{%0,%1,%2,%3},{%4,%5,%6,%7},{%8,%9},{%0,%1,%2,%3};"
        : "+f"(d[0]), "+f"(d[1]), "+f"(d[2]), "+f"(d[3])
        : "r"(a0), "r"(a1), "r"(a2), "r"(a3), "r"(b0), "r"(b1));
}

// ---------------------------------------------------------------------------
// Kernel 1: BN stats per (tile, channel=oc) + weight hi/lo split into g_w2.
// ---------------------------------------------------------------------------
__global__ __launch_bounds__(256) void bn_stats_kernel(
    const float* __restrict__ x,
    const float* __restrict__ gamma,
    const float* __restrict__ beta,
    const float* __restrict__ conv_w)
{
    const int bid = blockIdx.x;           // t*32 + c
    const int t = bid >> 5;
    const int c = bid & 31;
    const int ti = t >> 3, tj = t & 7;

    const float* base = x + (size_t)c * HW + (size_t)(ti * TH) * W_ + tj * TW;
    const size_t bstride = (size_t)C_ * HW;

    float s = 0.f, s2 = 0.f;
    for (int i = threadIdx.x; i < B_ * TH * 5; i += 256) {
        int b = i / (TH * 5);
        int r = i - b * (TH * 5);
        int y = r / 5, xq = r - y * 5;
        float4 v = *reinterpret_cast<const float4*>(
            &base[(size_t)b * bstride + y * W_ + xq * 4]);
        s  += (v.x + v.y) + (v.z + v.w);
        s2 += (v.x * v.x + v.y * v.y) + (v.z * v.z + v.w * v.w);
    }

    // weight split for oc = c: rows = tap*32 + ic, col = oc
    for (int i = threadIdx.x; i < 288; i += 256) {
        int ic = i / 9, tap = i - ic * 9;
        float w = conv_w[(((size_t)t * C_ + c) * C_ + ic) * 9 + tap];
        __nv_bfloat16 hi = __float2bfloat16(w);
        __nv_bfloat16 lo = __float2bfloat16(w - __bfloat162float(hi));
        uint32_t row = (uint32_t)(tap * 32 + ic);
        g_w2[t][sw128(row * 128 + c * 2) >> 1]      = hi;
        g_w2[t][sw128(row * 128 + 64 + c * 2) >> 1] = lo;
    }

    __shared__ float ss[256], ss2[256];
    ss[threadIdx.x] = s;
    ss2[threadIdx.x] = s2;
    __syncthreads();
    for (int off = 128; off > 0; off >>= 1) {
        if (threadIdx.x < off) {
            ss[threadIdx.x]  += ss[threadIdx.x + off];
            ss2[threadIdx.x] += ss2[threadIdx.x + off];
        }
        __syncthreads();
    }
    if (threadIdx.x == 0) {
        const float invN = 1.f / (float)(B_ * TH * TW);
        float mean = ss[0] * invN;
        float var  = ss2[0] * invN - mean * mean;
        float sc = gamma[bid] * rsqrtf(var + EPS);
        d_scale[bid] = sc;
        d_shift[bid] = beta[bid] - mean * sc;
    }
}

// ---------------------------------------------------------------------------
// Kernel 2: per-(tile, batch) implicit-GEMM 3x3 conv via mma.sync bf16 hi/lo.
// B fragments hoisted across 2 m-tiles per warp (static T=2, two passes).
// ---------------------------------------------------------------------------
__global__ __launch_bounds__(256, 2) void conv_kernel(
    const float* __restrict__ x,
    const float* __restrict__ conv_b,
    float* __restrict__ out)
{
    extern __shared__ char smem[];
    const uint32_t sbase = smem_u32(smem);
    const uint32_t hb = (sbase + 1023u) & ~1023u;
    const uint32_t wb = hb + H_BYTES;
    char* hptr = smem + (hb - sbase);
    char* wptr = smem + (wb - sbase);

    const int bid = blockIdx.x;     // t*32 + b
    const int t = bid >> 5;
    const int b = bid & 31;
    const int ti = t >> 3, tj = t & 7;
    const int tid = threadIdx.x;
    const int warp = tid >> 5;
    const int lane = tid & 31;

    // ---- zero h region (padding must be 0) ----
    {
        uint4 z = make_uint4(0, 0, 0, 0);
        uint4* hz = reinterpret_cast<uint4*>(hptr);
        for (int i = tid; i < H_BYTES / 16; i += 256) hz[i] = z;
    }

    // ---- copy pre-split weights (already in swizzled layout) ----
    {
        const uint4* gsrc = reinterpret_cast<const uint4*>(g_w2[t]);
        uint4* wdst = reinterpret_cast<uint4*>(wptr);
        for (int i = tid; i < W_BYTES / 16; i += 256) wdst[i] = gsrc[i];
    }
    __syncthreads();

    // ---- load x tile, BN+ReLU, split to bf16 hi/lo, store swizzled ----
    const size_t xtile = ((size_t)b * C_) * HW + (size_t)(ti * TH) * W_ + tj * TW;
    for (int i = tid; i < C_ * TH * 5; i += 256) {
        int c = i / 100;
        int rr = i - c * 100;
        int y = rr / 5, xq = rr - y * 5;
        float4 v = *reinterpret_cast<const float4*>(
            &x[xtile + (size_t)c * HW + y * W_ + xq * 4]);
        float sc = d_scale[t * C_ + c];
        float sh = d_shift[t * C_ + c];
        int row0 = (y + 1) * 24 + xq * 4 + 1;
        float vv[4] = {v.x, v.y, v.z, v.w};
#pragma unroll
        for (int k = 0; k < 4; k++) {
            float f = fmaxf(fmaf(vv[k], sc, sh), 0.f);
            __nv_bfloat16 hi = __float2bfloat16(f);
            __nv_bfloat16 lo = __float2bfloat16(f - __bfloat162float(hi));
            uint32_t off = (uint32_t)(row0 + k) * 128 + c * 2;
            *reinterpret_cast<__nv_bfloat16*>(hptr + sw128(off))      = hi;
            *reinterpret_cast<__nv_bfloat16*>(hptr + sw128(off + 64)) = lo;
        }
    }
    __syncthreads();

    // ---- warp-level implicit GEMM, T=2 tiles per warp, two passes ----
    const int li   = lane & 7;
    const int sel8 = (lane >> 3) & 1;
    const int selk = (lane >> 4) & 1;
    const int tg   = lane & 3;
    const int g    = lane >> 2;

    float cb0[4], cb1[4];
#pragma unroll
    for (int j = 0; j < 4; j++) {
        cb0[j] = conv_b[t * C_ + j * 8 + 2 * tg];
        cb1[j] = conv_b[t * C_ + j * 8 + 2 * tg + 1];
    }

    const size_t bb = (size_t)b * C_ * HW;
    const int gtile = (ti * TH) * W_ + tj * TW;

#pragma unroll 1
    for (int base = 0; base < 25; base += 16) {
        const int mt0 = base + 2 * warp;
        const int mt1 = mt0 + 1;
        const bool v0 = (mt0 < 25);
        const bool v1 = (mt1 < 25);
        if (!v0) break;

        // lane A-row base (padded coords) per tile
        int pr0, pr1;
        {
            int m = mt0 * 16 + li + sel8 * 8;
            int my = m / 20;
            pr0 = my * 24 + (m - my * 20);
        }
        {
            int mm = (v1 ? mt1 : mt0) * 16 + li + sel8 * 8;
            int my = mm / 20;
            pr1 = my * 24 + (mm - my * 20);
        }

        float acc0[4][4], acc1[4][4];
#pragma unroll
        for (int j = 0; j < 4; j++)
#pragma unroll
            for (int k = 0; k < 4; k++) { acc0[j][k] = 0.f; acc1[j][k] = 0.f; }

#pragma unroll 1
        for (int tap = 0; tap < 9; tap++) {
            const int dyx = (tap / 3) * 24 + (tap % 3);
            const uint32_t brow = wb + (uint32_t)(tap * 32 + li + sel8 * 8) * 128;
#pragma unroll
            for (int kc = 0; kc < 2; kc++) {
                // ---- B fragments: once per (tap,kc), shared by both tiles ----
                const uint32_t bro = brow + (uint32_t)(kc * 16) * 128;
                const uint32_t sb0 = (uint32_t)selk;          // n 0-15
                const uint32_t sb1 = (uint32_t)(2 + selk);    // n 16-31
                uint32_t bh[8], bl[8];
                ldm_x4_t(bro + ((sb0 ^ (uint32_t)li) << 4),       bh[0], bh[1], bh[2], bh[3]);
                ldm_x4_t(bro + ((sb1 ^ (uint32_t)li) << 4),       bh[4], bh[5], bh[6], bh[7]);
                ldm_x4_t(bro + (((sb0 + 4) ^ (uint32_t)li) << 4), bl[0], bl[1], bl[2], bl[3]);
                ldm_x4_t(bro + (((sb1 + 4) ^ (uint32_t)li) << 4), bl[4], bl[5], bl[6], bl[7]);

                const uint32_t sa = (uint32_t)(kc * 2 + selk);

                // ---- tile 0 ----
                {
                    const int inrow = pr0 + dyx;
                    const uint32_t arow = hb + (uint32_t)inrow * 128;
                    const uint32_t rx = (uint32_t)(inrow & 7);
                    uint32_t ah0, ah1, ah2, ah3, al0, al1, al2, al3;
                    ldm_x4(arow + ((sa ^ rx) << 4),        ah0, ah1, ah2, ah3);
                    ldm_x4(arow + (((sa + 4) ^ rx) << 4),  al0, al1, al2, al3);
#pragma unroll
                    for (int j = 0; j < 4; j++) {
                        mma16816(acc0[j], ah0, ah1, ah2, ah3, bh[2 * j], bh[2 * j + 1]);
                        mma16816(acc0[j], ah0, ah1, ah2, ah3, bl[2 * j], bl[2 * j + 1]);
                        mma16816(acc0[j], al0, al1, al2, al3, bh[2 * j], bh[2 * j + 1]);
                    }
                }
                // ---- tile 1 ----
                if (v1) {
                    const int inrow = pr1 + dyx;
                    const uint32_t arow = hb + (uint32_t)inrow * 128;
                    const uint32_t rx = (uint32_t)(inrow & 7);
                    uint32_t ah0, ah1, ah2, ah3, al0, al1, al2, al3;
                    ldm_x4(arow + ((sa ^ rx) << 4),        ah0, ah1, ah2, ah3);
                    ldm_x4(arow + (((sa + 4) ^ rx) << 4),  al0, al1, al2, al3);
#pragma unroll
                    for (int j = 0; j < 4; j++) {
                        mma16816(acc1[j], ah0, ah1, ah2, ah3, bh[2 * j], bh[2 * j + 1]);
                        mma16816(acc1[j], ah0, ah1, ah2, ah3, bl[2 * j], bl[2 * j + 1]);
                        mma16816(acc1[j], al0, al1, al2, al3, bh[2 * j], bh[2 * j + 1]);
                    }
                }
            }
        }

        // ---- epilogue for this pass ----
#pragma unroll 1
        for (int tt = 0; tt < 2; tt++) {
            if (tt == 1 && !v1) break;
            const int m0 = (tt == 0 ? mt0 : mt1) * 16;
            const int p0 = m0 + g;
            const int p1 = p0 + 8;
            const int y0 = p0 / 20, x0 = p0 - y0 * 20;
            const int y1 = p1 / 20, x1 = p1 - y1 * 20;
            const size_t pa0 = (size_t)(gtile + y0 * W_ + x0);
            const size_t pa1 = (size_t)(gtile + y1 * W_ + x1);
            float (*ac)[4] = (tt == 0) ? acc0 : acc1;
#pragma unroll
            for (int j = 0; j < 4; j++) {
                const int oc = j * 8 + 2 * tg;
                const size_t a00 = bb + (size_t)oc * HW + pa0;
                const size_t a10 = bb + (size_t)oc * HW + pa1;
                out[a00]      = ac[j][0] + cb0[j] + x[a00];
                out[a00 + HW] = ac[j][1] + cb1[j] + x[a00 + HW];
                out[a10]      = ac[j][2] + cb0[j] + x[a10];
                out[a10 + HW] = ac[j][3] + cb1[j] + x[a10 + HW];
            }
        }
    }
}

// ---------------------------------------------------------------------------
extern "C" void kernel_launch(void* const* d_in, const int* in_sizes, int n_in,
                              void* d_out, int out_size)
{
    const float* x      = (const float*)d_in[0];
    const float* gamma  = (const float*)d_in[1];
    const float* beta   = (const float*)d_in[2];
    const float* conv_w = (const float*)d_in[3];
    const float* conv_b = (const float*)d_in[4];
    float* out = (float*)d_out;

    bn_stats_kernel<<<NT * C_, 256>>>(x, gamma, beta, conv_w);

    cudaFuncSetAttribute(conv_kernel,
                         cudaFuncAttributeMaxDynamicSharedMemorySize, SMEM_REQ);
    conv_kernel<<<NT * B_, 256, SMEM_REQ>>>(x, conv_b, out);
}

// round 9
// speedup vs baseline: 1.9164x; 1.2494x over previous
#include <cuda_runtime.h>
#include <cuda_bf16.h>
#include <cstdint>

#define B_  32
#define C_  32
#define H_  160
#define W_  160
#define TH  20
#define TW  20
#define NT  64
#define EPS 1e-5f
#define HW  (H_ * W_)        // 25600

// H tile: 484 rows (22x22 padded pixels), 144B stride (128B content: hi 32ch | lo 32ch)
#define HSTRIDE 144
#define H_BYTES (484 * HSTRIDE)        // 69696
// Weights: 288 rows (tap*32+ic), 144B stride (hi oc0-31 | lo oc0-31)
#define W_BYTES (288 * HSTRIDE)        // 41472
#define SMEM_REQ (1024 + H_BYTES + W_BYTES + 256)   // 112448

__device__ float d_scale[NT * C_];
__device__ float d_shift[NT * C_];
// Pre-split weights in final smem layout: [row = tap*32+ic][72 bf16: hi oc | lo oc]
__device__ __align__(16) __nv_bfloat16 g_w2[NT][288 * 72];

__device__ __forceinline__ uint32_t smem_u32(const void* p) {
    uint32_t a;
    asm("{ .reg .u64 t; cvta.to.shared.u64 t, %1; cvt.u32.u64 %0, t; }" : "=r"(a) : "l"(p));
    return a;
}

__device__ __forceinline__ void ldm_x4(uint32_t addr,
                                       uint32_t& r0, uint32_t& r1,
                                       uint32_t& r2, uint32_t& r3) {
    asm volatile("ldmatrix.sync.aligned.m8n8.x4.shared.b16 {%0,%1,%2,%3}, [%4];"
                 : "=r"(r0), "=r"(r1), "=r"(r2), "=r"(r3) : "r"(addr));
}
__device__ __forceinline__ void ldm_x4_t(uint32_t addr,
                                         uint32_t& r0, uint32_t& r1,
                                         uint32_t& r2, uint32_t& r3) {
    asm volatile("ldmatrix.sync.aligned.m8n8.x4.trans.shared.b16 {%0,%1,%2,%3}, [%4];"
                 : "=r"(r0), "=r"(r1), "=r"(r2), "=r"(r3) : "r"(addr));
}
__device__ __forceinline__ void mma16816(float* d, uint32_t a0, uint32_t a1,
                                         uint32_t a2, uint32_t a3,
                                         uint32_t b0, uint32_t b1) {
    asm volatile(
        "mma.sync.aligned.m16n8k16.row.col.f32.bf16.bf16.f32 "
        "{%0,%1,%2,%3},{%4,%5,%6,%7},{%8,%9},{%0,%1,%2,%3};"
        : "+f"(d[0]), "+f"(d[1]), "+f"(d[2]), "+f"(d[3])
        : "r"(a0), "r"(a1), "r"(a2), "r"(a3), "r"(b0), "r"(b1));
}

// ---------------------------------------------------------------------------
// Kernel 1: BN stats per (tile, channel=oc) + weight hi/lo split into g_w2.
// ---------------------------------------------------------------------------
__global__ __launch_bounds__(256) void bn_stats_kernel(
    const float* __restrict__ x,
    const float* __restrict__ gamma,
    const float* __restrict__ beta,
    const float* __restrict__ conv_w)
{
    const int bid = blockIdx.x;           // t*32 + c
    const int t = bid >> 5;
    const int c = bid & 31;
    const int ti = t >> 3, tj = t & 7;

    const float* base = x + (size_t)c * HW + (size_t)(ti * TH) * W_ + tj * TW;
    const size_t bstride = (size_t)C_ * HW;

    float s = 0.f, s2 = 0.f;
    for (int i = threadIdx.x; i < B_ * TH * 5; i += 256) {
        int b = i / (TH * 5);
        int r = i - b * (TH * 5);
        int y = r / 5, xq = r - y * 5;
        float4 v = *reinterpret_cast<const float4*>(
            &base[(size_t)b * bstride + y * W_ + xq * 4]);
        s  += (v.x + v.y) + (v.z + v.w);
        s2 += (v.x * v.x + v.y * v.y) + (v.z * v.z + v.w * v.w);
    }

    // weight split for oc = c: row = tap*32 + ic; [hi oc | lo oc] per 72-bf16 row
    for (int i = threadIdx.x; i < 288; i += 256) {
        int ic = i / 9, tap = i - ic * 9;
        float w = conv_w[(((size_t)t * C_ + c) * C_ + ic) * 9 + tap];
        __nv_bfloat16 hi = __float2bfloat16(w);
        __nv_bfloat16 lo = __float2bfloat16(w - __bfloat162float(hi));
        int row = tap * 32 + ic;
        g_w2[t][row * 72 + c]      = hi;
        g_w2[t][row * 72 + 32 + c] = lo;
    }

    __shared__ float ss[256], ss2[256];
    ss[threadIdx.x] = s;
    ss2[threadIdx.x] = s2;
    __syncthreads();
    for (int off = 128; off > 0; off >>= 1) {
        if (threadIdx.x < off) {
            ss[threadIdx.x]  += ss[threadIdx.x + off];
            ss2[threadIdx.x] += ss2[threadIdx.x + off];
        }
        __syncthreads();
    }
    if (threadIdx.x == 0) {
        const float invN = 1.f / (float)(B_ * TH * TW);
        float mean = ss[0] * invN;
        float var  = ss2[0] * invN - mean * mean;
        float sc = gamma[bid] * rsqrtf(var + EPS);
        d_scale[bid] = sc;
        d_shift[bid] = beta[bid] - mean * sc;
    }
}

// ---------------------------------------------------------------------------
// Kernel 2: per-(tile, batch) implicit-GEMM 3x3 conv via mma.sync bf16 hi/lo.
// Padded-stride smem (conflict-free ldmatrix), quad-channel STS.64 prologue,
// B fragments hoisted across 2 m-tiles per warp.
// ---------------------------------------------------------------------------
__global__ __launch_bounds__(256, 2) void conv_kernel(
    const float* __restrict__ x,
    const float* __restrict__ conv_b,
    float* __restrict__ out)
{
    extern __shared__ char smem[];
    const uint32_t sbase = smem_u32(smem);
    const uint32_t hb = (sbase + 1023u) & ~1023u;
    const uint32_t wb = hb + H_BYTES;
    char* hptr = smem + (hb - sbase);
    char* wptr = smem + (wb - sbase);
    // BN params staged AFTER the weight region (R8 bug: aliased h at smem base)
    float* sscale = reinterpret_cast<float*>(smem + (wb - sbase) + W_BYTES);
    float* sshift = sscale + 32;

    const int bid = blockIdx.x;     // t*32 + b
    const int t = bid >> 5;
    const int b = bid & 31;
    const int ti = t >> 3, tj = t & 7;
    const int tid = threadIdx.x;
    const int warp = tid >> 5;
    const int lane = tid & 31;

    // ---- stage BN params ----
    if (tid < 32) {
        sscale[tid] = d_scale[t * C_ + tid];
        sshift[tid] = d_shift[t * C_ + tid];
    }

    // ---- zero h region (halo must be 0) ----
    {
        uint4 z = make_uint4(0, 0, 0, 0);
        uint4* hz = reinterpret_cast<uint4*>(hptr);
        for (int i = tid; i < H_BYTES / 16; i += 256) hz[i] = z;
    }

    // ---- copy pre-split weights (already in final layout) ----
    {
        const uint4* gsrc = reinterpret_cast<const uint4*>(g_w2[t]);
        uint4* wdst = reinterpret_cast<uint4*>(wptr);
        for (int i = tid; i < W_BYTES / 16; i += 256) wdst[i] = gsrc[i];
    }
    __syncthreads();

    // ---- prologue: thread = 4 channels x 1 pixel -> two STS.64 ----
    const size_t xtile = ((size_t)b * C_) * HW + (size_t)(ti * TH) * W_ + tj * TW;
    for (int i = tid; i < 8 * TH * TW; i += 256) {   // 3200 work items
        int p  = i % 400;          // pixel
        int cq = i / 400;          // channel quad
        int py = p / 20, px = p - py * 20;
        int c0 = cq * 4;
        const float* xp = &x[xtile + (size_t)c0 * HW + py * W_ + px];
        uint32_t hrow = (uint32_t)((py + 1) * 22 + px + 1) * HSTRIDE;
        __nv_bfloat16 hq[4], lq[4];
#pragma unroll
        for (int j = 0; j < 4; j++) {
            float f = fmaxf(fmaf(xp[(size_t)j * HW], sscale[c0 + j], sshift[c0 + j]), 0.f);
            hq[j] = __float2bfloat16(f);
            lq[j] = __float2bfloat16(f - __bfloat162float(hq[j]));
        }
        *reinterpret_cast<uint64_t*>(hptr + hrow + cq * 8)      = *reinterpret_cast<uint64_t*>(hq);
        *reinterpret_cast<uint64_t*>(hptr + hrow + 64 + cq * 8) = *reinterpret_cast<uint64_t*>(lq);
    }
    __syncthreads();

    // ---- warp-level implicit GEMM, T=2 tiles per warp, two passes ----
    const int li   = lane & 7;
    const int sel8 = (lane >> 3) & 1;
    const int selk = (lane >> 4) & 1;
    const int tg   = lane & 3;
    const int g    = lane >> 2;

    float cb0[4], cb1[4];
#pragma unroll
    for (int j = 0; j < 4; j++) {
        cb0[j] = conv_b[t * C_ + j * 8 + 2 * tg];
        cb1[j] = conv_b[t * C_ + j * 8 + 2 * tg + 1];
    }

    const size_t bb = (size_t)b * C_ * HW;
    const int gtile = (ti * TH) * W_ + tj * TW;

#pragma unroll 1
    for (int base = 0; base < 25; base += 16) {
        const int mt0 = base + 2 * warp;
        const int mt1 = mt0 + 1;
        const bool v0 = (mt0 < 25);
        const bool v1 = (mt1 < 25);
        if (!v0) break;

        // lane A-row base (padded coords) per tile
        int pr0, pr1;
        {
            int m = mt0 * 16 + li + sel8 * 8;
            int my = m / 20;
            pr0 = my * 22 + (m - my * 20);
        }
        {
            int mm = (v1 ? mt1 : mt0) * 16 + li + sel8 * 8;
            int my = mm / 20;
            pr1 = my * 22 + (mm - my * 20);
        }

        float acc0[4][4], acc1[4][4];
#pragma unroll
        for (int j = 0; j < 4; j++)
#pragma unroll
            for (int k = 0; k < 4; k++) { acc0[j][k] = 0.f; acc1[j][k] = 0.f; }

#pragma unroll 1
        for (int tap = 0; tap < 9; tap++) {
            const int dyx = (tap / 3) * 22 + (tap % 3);
#pragma unroll
            for (int kc = 0; kc < 2; kc++) {
                // ---- B fragments: once per (tap,kc), shared by both tiles ----
                const uint32_t brow = wb
                    + (uint32_t)(tap * 32 + kc * 16 + li + sel8 * 8) * HSTRIDE;
                const uint32_t cb_ = (uint32_t)selk * 16;
                uint32_t bh[8], bl[8];
                ldm_x4_t(brow + cb_,       bh[0], bh[1], bh[2], bh[3]);
                ldm_x4_t(brow + cb_ + 32,  bh[4], bh[5], bh[6], bh[7]);
                ldm_x4_t(brow + cb_ + 64,  bl[0], bl[1], bl[2], bl[3]);
                ldm_x4_t(brow + cb_ + 96,  bl[4], bl[5], bl[6], bl[7]);

                const uint32_t ca = (uint32_t)(kc * 2 + selk) * 16;

                // ---- tile 0 ----
                {
                    const uint32_t arow = hb + (uint32_t)(pr0 + dyx) * HSTRIDE;
                    uint32_t ah0, ah1, ah2, ah3, al0, al1, al2, al3;
                    ldm_x4(arow + ca,       ah0, ah1, ah2, ah3);
                    ldm_x4(arow + ca + 64,  al0, al1, al2, al3);
#pragma unroll
                    for (int j = 0; j < 4; j++) {
                        mma16816(acc0[j], ah0, ah1, ah2, ah3, bh[2 * j], bh[2 * j + 1]);
                        mma16816(acc0[j], ah0, ah1, ah2, ah3, bl[2 * j], bl[2 * j + 1]);
                        mma16816(acc0[j], al0, al1, al2, al3, bh[2 * j], bh[2 * j + 1]);
                    }
                }
                // ---- tile 1 ----
                if (v1) {
                    const uint32_t arow = hb + (uint32_t)(pr1 + dyx) * HSTRIDE;
                    uint32_t ah0, ah1, ah2, ah3, al0, al1, al2, al3;
                    ldm_x4(arow + ca,       ah0, ah1, ah2, ah3);
                    ldm_x4(arow + ca + 64,  al0, al1, al2, al3);
#pragma unroll
                    for (int j = 0; j < 4; j++) {
                        mma16816(acc1[j], ah0, ah1, ah2, ah3, bh[2 * j], bh[2 * j + 1]);
                        mma16816(acc1[j], ah0, ah1, ah2, ah3, bl[2 * j], bl[2 * j + 1]);
                        mma16816(acc1[j], al0, al1, al2, al3, bh[2 * j], bh[2 * j + 1]);
                    }
                }
            }
        }

        // ---- epilogue for this pass ----
#pragma unroll 1
        for (int tt = 0; tt < 2; tt++) {
            if (tt == 1 && !v1) break;
            const int m0 = (tt == 0 ? mt0 : mt1) * 16;
            const int p0 = m0 + g;
            const int p1 = p0 + 8;
            const int y0 = p0 / 20, x0 = p0 - y0 * 20;
            const int y1 = p1 / 20, x1 = p1 - y1 * 20;
            const size_t pa0 = (size_t)(gtile + y0 * W_ + x0);
            const size_t pa1 = (size_t)(gtile + y1 * W_ + x1);
            float (*ac)[4] = (tt == 0) ? acc0 : acc1;
#pragma unroll
            for (int j = 0; j < 4; j++) {
                const int oc = j * 8 + 2 * tg;
                const size_t a00 = bb + (size_t)oc * HW + pa0;
                const size_t a10 = bb + (size_t)oc * HW + pa1;
                out[a00]      = ac[j][0] + cb0[j] + x[a00];
                out[a00 + HW] = ac[j][1] + cb1[j] + x[a00 + HW];
                out[a10]      = ac[j][2] + cb0[j] + x[a10];
                out[a10 + HW] = ac[j][3] + cb1[j] + x[a10 + HW];
            }
        }
    }
}

// ---------------------------------------------------------------------------
extern "C" void kernel_launch(void* const* d_in, const int* in_sizes, int n_in,
                              void* d_out, int out_size)
{
    const float* x      = (const float*)d_in[0];
    const float* gamma  = (const float*)d_in[1];
    const float* beta   = (const float*)d_in[2];
    const float* conv_w = (const float*)d_in[3];
    const float* conv_b = (const float*)d_in[4];
    float* out = (float*)d_out;

    bn_stats_kernel<<<NT * C_, 256>>>(x, gamma, beta, conv_w);

    cudaFuncSetAttribute(conv_kernel,
                         cudaFuncAttributeMaxDynamicSharedMemorySize, SMEM_REQ);
    conv_kernel<<<NT * B_, 256, SMEM_REQ>>>(x, conv_b, out);
}

// round 10
// speedup vs baseline: 2.0350x; 1.0619x over previous
#include <cuda_runtime.h>
#include <cuda_bf16.h>
#include <cstdint>

#define B_  32
#define C_  32
#define H_  160
#define W_  160
#define TH  20
#define TW  20
#define NT  64
#define EPS 1e-5f
#define HW  (H_ * W_)        // 25600

#define NTHREADS 384

// H tile: 484 rows (22x22 padded pixels), 144B stride (128B content: hi 32ch | lo 32ch)
#define HSTRIDE 144
#define H_BYTES (484 * HSTRIDE)        // 69696
// Weights: 288 rows (tap*32+ic), 144B stride (hi oc0-31 | lo oc0-31)
#define W_BYTES (288 * HSTRIDE)        // 41472
#define SMEM_REQ (1024 + H_BYTES + W_BYTES + 256)   // 112448

__device__ float d_scale[NT * C_];
__device__ float d_shift[NT * C_];
// Pre-split weights in final smem layout: [row = tap*32+ic][72 bf16: hi oc | lo oc]
__device__ __align__(16) __nv_bfloat16 g_w2[NT][288 * 72];

__device__ __forceinline__ uint32_t smem_u32(const void* p) {
    uint32_t a;
    asm("{ .reg .u64 t; cvta.to.shared.u64 t, %1; cvt.u32.u64 %0, t; }" : "=r"(a) : "l"(p));
    return a;
}

__device__ __forceinline__ void ldm_x4(uint32_t addr,
                                       uint32_t& r0, uint32_t& r1,
                                       uint32_t& r2, uint32_t& r3) {
    asm volatile("ldmatrix.sync.aligned.m8n8.x4.shared.b16 {%0,%1,%2,%3}, [%4];"
                 : "=r"(r0), "=r"(r1), "=r"(r2), "=r"(r3) : "r"(addr));
}
__device__ __forceinline__ void ldm_x4_t(uint32_t addr,
                                         uint32_t& r0, uint32_t& r1,
                                         uint32_t& r2, uint32_t& r3) {
    asm volatile("ldmatrix.sync.aligned.m8n8.x4.trans.shared.b16 {%0,%1,%2,%3}, [%4];"
                 : "=r"(r0), "=r"(r1), "=r"(r2), "=r"(r3) : "r"(addr));
}
__device__ __forceinline__ void mma16816(float* d, uint32_t a0, uint32_t a1,
                                         uint32_t a2, uint32_t a3,
                                         uint32_t b0, uint32_t b1) {
    asm volatile(
        "mma.sync.aligned.m16n8k16.row.col.f32.bf16.bf16.f32 "
        "{%0,%1,%2,%3},{%4,%5,%6,%7},{%8,%9},{%0,%1,%2,%3};"
        : "+f"(d[0]), "+f"(d[1]), "+f"(d[2]), "+f"(d[3])
        : "r"(a0), "r"(a1), "r"(a2), "r"(a3), "r"(b0), "r"(b1));
}

// ---------------------------------------------------------------------------
// Kernel 1: BN stats per (tile, channel=oc) + weight hi/lo split into g_w2.
// ---------------------------------------------------------------------------
__global__ __launch_bounds__(256) void bn_stats_kernel(
    const float* __restrict__ x,
    const float* __restrict__ gamma,
    const float* __restrict__ beta,
    const float* __restrict__ conv_w)
{
    const int bid = blockIdx.x;           // t*32 + c
    const int t = bid >> 5;
    const int c = bid & 31;
    const int ti = t >> 3, tj = t & 7;

    const float* base = x + (size_t)c * HW + (size_t)(ti * TH) * W_ + tj * TW;
    const size_t bstride = (size_t)C_ * HW;

    float s = 0.f, s2 = 0.f;
    for (int i = threadIdx.x; i < B_ * TH * 5; i += 256) {
        int b = i / (TH * 5);
        int r = i - b * (TH * 5);
        int y = r / 5, xq = r - y * 5;
        float4 v = *reinterpret_cast<const float4*>(
            &base[(size_t)b * bstride + y * W_ + xq * 4]);
        s  += (v.x + v.y) + (v.z + v.w);
        s2 += (v.x * v.x + v.y * v.y) + (v.z * v.z + v.w * v.w);
    }

    // weight split for oc = c: row = tap*32 + ic; [hi oc | lo oc] per 72-bf16 row
    for (int i = threadIdx.x; i < 288; i += 256) {
        int ic = i / 9, tap = i - ic * 9;
        float w = conv_w[(((size_t)t * C_ + c) * C_ + ic) * 9 + tap];
        __nv_bfloat16 hi = __float2bfloat16(w);
        __nv_bfloat16 lo = __float2bfloat16(w - __bfloat162float(hi));
        int row = tap * 32 + ic;
        g_w2[t][row * 72 + c]      = hi;
        g_w2[t][row * 72 + 32 + c] = lo;
    }

    __shared__ float ss[256], ss2[256];
    ss[threadIdx.x] = s;
    ss2[threadIdx.x] = s2;
    __syncthreads();
    for (int off = 128; off > 0; off >>= 1) {
        if (threadIdx.x < off) {
            ss[threadIdx.x]  += ss[threadIdx.x + off];
            ss2[threadIdx.x] += ss2[threadIdx.x + off];
        }
        __syncthreads();
    }
    if (threadIdx.x == 0) {
        const float invN = 1.f / (float)(B_ * TH * TW);
        float mean = ss[0] * invN;
        float var  = ss2[0] * invN - mean * mean;
        float sc = gamma[bid] * rsqrtf(var + EPS);
        d_scale[bid] = sc;
        d_shift[bid] = beta[bid] - mean * sc;
    }
}

// ---------------------------------------------------------------------------
// Kernel 2: per-(tile, batch) implicit-GEMM 3x3 conv via mma.sync bf16 hi/lo.
// 384 threads (12 warps) for occupancy: 24 warps/SM at 2 CTAs/SM.
// ---------------------------------------------------------------------------
__global__ __launch_bounds__(NTHREADS, 2) void conv_kernel(
    const float* __restrict__ x,
    const float* __restrict__ conv_b,
    float* __restrict__ out)
{
    extern __shared__ char smem[];
    const uint32_t sbase = smem_u32(smem);
    const uint32_t hb = (sbase + 1023u) & ~1023u;
    const uint32_t wb = hb + H_BYTES;
    char* hptr = smem + (hb - sbase);
    char* wptr = smem + (wb - sbase);
    float* sscale = reinterpret_cast<float*>(smem + (wb - sbase) + W_BYTES);
    float* sshift = sscale + 32;

    const int bid = blockIdx.x;     // t*32 + b
    const int t = bid >> 5;
    const int b = bid & 31;
    const int ti = t >> 3, tj = t & 7;
    const int tid = threadIdx.x;
    const int warp = tid >> 5;
    const int lane = tid & 31;

    // ---- stage BN params ----
    if (tid < 32) {
        sscale[tid] = d_scale[t * C_ + tid];
        sshift[tid] = d_shift[t * C_ + tid];
    }

    // ---- zero h region (halo must be 0) ----
    {
        uint4 z = make_uint4(0, 0, 0, 0);
        uint4* hz = reinterpret_cast<uint4*>(hptr);
        for (int i = tid; i < H_BYTES / 16; i += NTHREADS) hz[i] = z;
    }

    // ---- copy pre-split weights (already in final layout) ----
    {
        const uint4* gsrc = reinterpret_cast<const uint4*>(g_w2[t]);
        uint4* wdst = reinterpret_cast<uint4*>(wptr);
        for (int i = tid; i < W_BYTES / 16; i += NTHREADS) wdst[i] = gsrc[i];
    }
    __syncthreads();

    // ---- prologue: thread = 4 channels x 1 pixel -> two STS.64 ----
    const size_t xtile = ((size_t)b * C_) * HW + (size_t)(ti * TH) * W_ + tj * TW;
    for (int i = tid; i < 8 * TH * TW; i += NTHREADS) {   // 3200 work items
        int p  = i % 400;          // pixel
        int cq = i / 400;          // channel quad
        int py = p / 20, px = p - py * 20;
        int c0 = cq * 4;
        const float* xp = &x[xtile + (size_t)c0 * HW + py * W_ + px];
        uint32_t hrow = (uint32_t)((py + 1) * 22 + px + 1) * HSTRIDE;
        __nv_bfloat16 hq[4], lq[4];
#pragma unroll
        for (int j = 0; j < 4; j++) {
            float f = fmaxf(fmaf(xp[(size_t)j * HW], sscale[c0 + j], sshift[c0 + j]), 0.f);
            hq[j] = __float2bfloat16(f);
            lq[j] = __float2bfloat16(f - __bfloat162float(hq[j]));
        }
        *reinterpret_cast<uint64_t*>(hptr + hrow + cq * 8)      = *reinterpret_cast<uint64_t*>(hq);
        *reinterpret_cast<uint64_t*>(hptr + hrow + 64 + cq * 8) = *reinterpret_cast<uint64_t*>(lq);
    }
    __syncthreads();

    // ---- warp-level implicit GEMM, T=2 tiles per warp ----
    // pass 1 (base=0): 12 warps x 2 tiles = tiles 0..23
    // pass 2 (base=24): warp 0 does tile 24
    const int li   = lane & 7;
    const int sel8 = (lane >> 3) & 1;
    const int selk = (lane >> 4) & 1;
    const int tg   = lane & 3;
    const int g    = lane >> 2;

    float cb0[4], cb1[4];
#pragma unroll
    for (int j = 0; j < 4; j++) {
        cb0[j] = conv_b[t * C_ + j * 8 + 2 * tg];
        cb1[j] = conv_b[t * C_ + j * 8 + 2 * tg + 1];
    }

    const size_t bb = (size_t)b * C_ * HW;
    const int gtile = (ti * TH) * W_ + tj * TW;

#pragma unroll 1
    for (int base = 0; base < 25; base += 24) {
        const int mt0 = base + 2 * warp;
        const int mt1 = mt0 + 1;
        const bool v0 = (mt0 < 25);
        const bool v1 = (mt1 < 25);
        if (!v0) break;

        // lane A-row base (padded coords) per tile
        int pr0, pr1;
        {
            int m = mt0 * 16 + li + sel8 * 8;
            int my = m / 20;
            pr0 = my * 22 + (m - my * 20);
        }
        {
            int mm = (v1 ? mt1 : mt0) * 16 + li + sel8 * 8;
            int my = mm / 20;
            pr1 = my * 22 + (mm - my * 20);
        }

        float acc0[4][4], acc1[4][4];
#pragma unroll
        for (int j = 0; j < 4; j++)
#pragma unroll
            for (int k = 0; k < 4; k++) { acc0[j][k] = 0.f; acc1[j][k] = 0.f; }

#pragma unroll 1
        for (int tap = 0; tap < 9; tap++) {
            const int dyx = (tap / 3) * 22 + (tap % 3);
#pragma unroll
            for (int kc = 0; kc < 2; kc++) {
                // ---- B fragments: once per (tap,kc), shared by both tiles ----
                const uint32_t brow = wb
                    + (uint32_t)(tap * 32 + kc * 16 + li + sel8 * 8) * HSTRIDE;
                const uint32_t cb_ = (uint32_t)selk * 16;
                uint32_t bh[8], bl[8];
                ldm_x4_t(brow + cb_,       bh[0], bh[1], bh[2], bh[3]);
                ldm_x4_t(brow + cb_ + 32,  bh[4], bh[5], bh[6], bh[7]);
                ldm_x4_t(brow + cb_ + 64,  bl[0], bl[1], bl[2], bl[3]);
                ldm_x4_t(brow + cb_ + 96,  bl[4], bl[5], bl[6], bl[7]);

                const uint32_t ca = (uint32_t)(kc * 2 + selk) * 16;

                // ---- tile 0 ----
                {
                    const uint32_t arow = hb + (uint32_t)(pr0 + dyx) * HSTRIDE;
                    uint32_t ah0, ah1, ah2, ah3, al0, al1, al2, al3;
                    ldm_x4(arow + ca,       ah0, ah1, ah2, ah3);
                    ldm_x4(arow + ca + 64,  al0, al1, al2, al3);
#pragma unroll
                    for (int j = 0; j < 4; j++) {
                        mma16816(acc0[j], ah0, ah1, ah2, ah3, bh[2 * j], bh[2 * j + 1]);
                        mma16816(acc0[j], ah0, ah1, ah2, ah3, bl[2 * j], bl[2 * j + 1]);
                        mma16816(acc0[j], al0, al1, al2, al3, bh[2 * j], bh[2 * j + 1]);
                    }
                }
                // ---- tile 1 ----
                if (v1) {
                    const uint32_t arow = hb + (uint32_t)(pr1 + dyx) * HSTRIDE;
                    uint32_t ah0, ah1, ah2, ah3, al0, al1, al2, al3;
                    ldm_x4(arow + ca,       ah0, ah1, ah2, ah3);
                    ldm_x4(arow + ca + 64,  al0, al1, al2, al3);
#pragma unroll
                    for (int j = 0; j < 4; j++) {
                        mma16816(acc1[j], ah0, ah1, ah2, ah3, bh[2 * j], bh[2 * j + 1]);
                        mma16816(acc1[j], ah0, ah1, ah2, ah3, bl[2 * j], bl[2 * j + 1]);
                        mma16816(acc1[j], al0, al1, al2, al3, bh[2 * j], bh[2 * j + 1]);
                    }
                }
            }
        }

        // ---- epilogue for this pass ----
#pragma unroll 1
        for (int tt = 0; tt < 2; tt++) {
            if (tt == 1 && !v1) break;
            const int m0 = (tt == 0 ? mt0 : mt1) * 16;
            const int p0 = m0 + g;
            const int p1 = p0 + 8;
            const int y0 = p0 / 20, x0 = p0 - y0 * 20;
            const int y1 = p1 / 20, x1 = p1 - y1 * 20;
            const size_t pa0 = (size_t)(gtile + y0 * W_ + x0);
            const size_t pa1 = (size_t)(gtile + y1 * W_ + x1);
            float (*ac)[4] = (tt == 0) ? acc0 : acc1;
#pragma unroll
            for (int j = 0; j < 4; j++) {
                const int oc = j * 8 + 2 * tg;
                const size_t a00 = bb + (size_t)oc * HW + pa0;
                const size_t a10 = bb + (size_t)oc * HW + pa1;
                out[a00]      = ac[j][0] + cb0[j] + x[a00];
                out[a00 + HW] = ac[j][1] + cb1[j] + x[a00 + HW];
                out[a10]      = ac[j][2] + cb0[j] + x[a10];
                out[a10 + HW] = ac[j][3] + cb1[j] + x[a10 + HW];
            }
        }
    }
}

// ---------------------------------------------------------------------------
extern "C" void kernel_launch(void* const* d_in, const int* in_sizes, int n_in,
                              void* d_out, int out_size)
{
    const float* x      = (const float*)d_in[0];
    const float* gamma  = (const float*)d_in[1];
    const float* beta   = (const float*)d_in[2];
    const float* conv_w = (const float*)d_in[3];
    const float* conv_b = (const float*)d_in[4];
    float* out = (float*)d_out;

    bn_stats_kernel<<<NT * C_, 256>>>(x, gamma, beta, conv_w);

    cudaFuncSetAttribute(conv_kernel,
                         cudaFuncAttributeMaxDynamicSharedMemorySize, SMEM_REQ);
    conv_kernel<<<NT * B_, NTHREADS, SMEM_REQ>>>(x, conv_b, out);
}

// round 12
// speedup vs baseline: 2.8433x; 1.3972x over previous
#include <cuda_runtime.h>
#include <cuda_fp16.h>
#include <cstdint>

#define B_  32
#define C_  32
#define H_  160
#define W_  160
#define TH  20
#define TW  20
#define NT  64
#define EPS 1e-5f
#define HW  (H_ * W_)        // 25600

#define NTHREADS 384

// H tile: 484 rows (22x22 padded pixels), 80B stride (64B content: 32ch fp16)
#define HSTRIDE 80
#define H_BYTES (484 * HSTRIDE)        // 38720
// Weights: 288 rows (tap*32+ic), 80B stride (32 oc fp16 = 64B content)
#define W_BYTES (288 * HSTRIDE)        // 23040
#define SMEM_REQ (1024 + H_BYTES + W_BYTES + 256)   // 63040

__device__ float d_scale[NT * C_];
__device__ float d_shift[NT * C_];
// fp16 weights: [row = tap*32+ic][32 oc fp16]
__device__ __align__(16) __half g_w2[NT][288 * 32];

__device__ __forceinline__ uint32_t smem_u32(const void* p) {
    uint32_t a;
    asm("{ .reg .u64 t; cvta.to.shared.u64 t, %1; cvt.u32.u64 %0, t; }" : "=r"(a) : "l"(p));
    return a;
}

__device__ __forceinline__ void ldm_x4(uint32_t addr,
                                       uint32_t& r0, uint32_t& r1,
                                       uint32_t& r2, uint32_t& r3) {
    asm volatile("ldmatrix.sync.aligned.m8n8.x4.shared.b16 {%0,%1,%2,%3}, [%4];"
                 : "=r"(r0), "=r"(r1), "=r"(r2), "=r"(r3) : "r"(addr));
}
__device__ __forceinline__ void ldm_x4_t(uint32_t addr,
                                         uint32_t& r0, uint32_t& r1,
                                         uint32_t& r2, uint32_t& r3) {
    asm volatile("ldmatrix.sync.aligned.m8n8.x4.trans.shared.b16 {%0,%1,%2,%3}, [%4];"
                 : "=r"(r0), "=r"(r1), "=r"(r2), "=r"(r3) : "r"(addr));
}
__device__ __forceinline__ void mma16816(float* d, uint32_t a0, uint32_t a1,
                                         uint32_t a2, uint32_t a3,
                                         uint32_t b0, uint32_t b1) {
    asm volatile(
        "mma.sync.aligned.m16n8k16.row.col.f32.f16.f16.f32 "
        "{%0,%1,%2,%3},{%4,%5,%6,%7},{%8,%9},{%0,%1,%2,%3};"
        : "+f"(d[0]), "+f"(d[1]), "+f"(d[2]), "+f"(d[3])
        : "r"(a0), "r"(a1), "r"(a2), "r"(a3), "r"(b0), "r"(b1));
}

// ---------------------------------------------------------------------------
// Kernel 1: BN stats per (tile, channel=oc) + fp16 weight pack into g_w2.
// ---------------------------------------------------------------------------
__global__ __launch_bounds__(256) void bn_stats_kernel(
    const float* __restrict__ x,
    const float* __restrict__ gamma,
    const float* __restrict__ beta,
    const float* __restrict__ conv_w)
{
    const int bid = blockIdx.x;           // t*32 + c
    const int t = bid >> 5;
    const int c = bid & 31;
    const int ti = t >> 3, tj = t & 7;

    const float* base = x + (size_t)c * HW + (size_t)(ti * TH) * W_ + tj * TW;
    const size_t bstride = (size_t)C_ * HW;

    float s = 0.f, s2 = 0.f;
    for (int i = threadIdx.x; i < B_ * TH * 5; i += 256) {
        int b = i / (TH * 5);
        int r = i - b * (TH * 5);
        int y = r / 5, xq = r - y * 5;
        float4 v = *reinterpret_cast<const float4*>(
            &base[(size_t)b * bstride + y * W_ + xq * 4]);
        s  += (v.x + v.y) + (v.z + v.w);
        s2 += (v.x * v.x + v.y * v.y) + (v.z * v.z + v.w * v.w);
    }

    // weight pack for oc = c: row = tap*32 + ic
    for (int i = threadIdx.x; i < 288; i += 256) {
        int ic = i / 9, tap = i - ic * 9;
        float w = conv_w[(((size_t)t * C_ + c) * C_ + ic) * 9 + tap];
        g_w2[t][(tap * 32 + ic) * 32 + c] = __float2half(w);
    }

    __shared__ float ss[256], ss2[256];
    ss[threadIdx.x] = s;
    ss2[threadIdx.x] = s2;
    __syncthreads();
    for (int off = 128; off > 0; off >>= 1) {
        if (threadIdx.x < off) {
            ss[threadIdx.x]  += ss[threadIdx.x + off];
            ss2[threadIdx.x] += ss2[threadIdx.x + off];
        }
        __syncthreads();
    }
    if (threadIdx.x == 0) {
        const float invN = 1.f / (float)(B_ * TH * TW);
        float mean = ss[0] * invN;
        float var  = ss2[0] * invN - mean * mean;
        float sc = gamma[bid] * rsqrtf(var + EPS);
        d_scale[bid] = sc;
        d_shift[bid] = beta[bid] - mean * sc;
    }
}

// ---------------------------------------------------------------------------
// Kernel 2: per-(tile, batch) implicit-GEMM 3x3 conv via fp16 mma.sync.
// 384 threads; padded-stride smem; B hoisted across 2 m-tiles per warp.
// ---------------------------------------------------------------------------
__global__ __launch_bounds__(NTHREADS, 2) void conv_kernel(
    const float* __restrict__ x,
    const float* __restrict__ conv_b,
    float* __restrict__ out)
{
    extern __shared__ char smem[];
    const uint32_t sbase = smem_u32(smem);
    const uint32_t hb = (sbase + 1023u) & ~1023u;
    const uint32_t wb = hb + H_BYTES;
    char* hptr = smem + (hb - sbase);
    char* wptr = smem + (wb - sbase);
    float* sscale = reinterpret_cast<float*>(smem + (wb - sbase) + W_BYTES);
    float* sshift = sscale + 32;

    const int bid = blockIdx.x;     // t*32 + b
    const int t = bid >> 5;
    const int b = bid & 31;
    const int ti = t >> 3, tj = t & 7;
    const int tid = threadIdx.x;
    const int warp = tid >> 5;
    const int lane = tid & 31;

    // ---- stage BN params ----
    if (tid < 32) {
        sscale[tid] = d_scale[t * C_ + tid];
        sshift[tid] = d_shift[t * C_ + tid];
    }

    // ---- zero h region (halo must be 0) ----
    {
        uint4 z = make_uint4(0, 0, 0, 0);
        uint4* hz = reinterpret_cast<uint4*>(hptr);
        for (int i = tid; i < H_BYTES / 16; i += NTHREADS) hz[i] = z;
    }

    // ---- copy fp16 weights: 288 rows x 64B content (2 x 32B chunks) ----
    {
        const uint4* gsrc = reinterpret_cast<const uint4*>(g_w2[t]);
        uint4* wdst = reinterpret_cast<uint4*>(wptr);
        for (int i = tid; i < 288 * 2; i += NTHREADS) {   // FIX: was W_BYTES/16
            int row = i >> 1, hf = i & 1;
            wdst[(row * HSTRIDE + hf * 32) >> 4]     = gsrc[(row * 64 + hf * 32) >> 4];
            wdst[((row * HSTRIDE + hf * 32) >> 4) + 1] = gsrc[((row * 64 + hf * 32) >> 4) + 1];
        }
    }
    __syncthreads();

    // ---- prologue: thread = 4 channels x 1 pixel -> one STS.64 ----
    const size_t xtile = ((size_t)b * C_) * HW + (size_t)(ti * TH) * W_ + tj * TW;
    for (int i = tid; i < 8 * TH * TW; i += NTHREADS) {   // 3200 work items
        int p  = i % 400;          // pixel
        int cq = i / 400;          // channel quad
        int py = p / 20, px = p - py * 20;
        int c0 = cq * 4;
        const float* xp = &x[xtile + (size_t)c0 * HW + py * W_ + px];
        uint32_t hrow = (uint32_t)((py + 1) * 22 + px + 1) * HSTRIDE;
        __half hq[4];
#pragma unroll
        for (int j = 0; j < 4; j++) {
            float f = fmaxf(fmaf(xp[(size_t)j * HW], sscale[c0 + j], sshift[c0 + j]), 0.f);
            hq[j] = __float2half(f);
        }
        *reinterpret_cast<uint64_t*>(hptr + hrow + cq * 8) = *reinterpret_cast<uint64_t*>(hq);
    }
    __syncthreads();

    // ---- warp-level implicit GEMM, T=2 tiles per warp ----
    const int li   = lane & 7;
    const int sel8 = (lane >> 3) & 1;
    const int selk = (lane >> 4) & 1;
    const int tg   = lane & 3;
    const int g    = lane >> 2;

    float cb0[4], cb1[4];
#pragma unroll
    for (int j = 0; j < 4; j++) {
        cb0[j] = conv_b[t * C_ + j * 8 + 2 * tg];
        cb1[j] = conv_b[t * C_ + j * 8 + 2 * tg + 1];
    }

    const size_t bb = (size_t)b * C_ * HW;
    const int gtile = (ti * TH) * W_ + tj * TW;

#pragma unroll 1
    for (int base = 0; base < 25; base += 24) {
        const int mt0 = base + 2 * warp;
        const int mt1 = mt0 + 1;
        const bool v0 = (mt0 < 25);
        const bool v1 = (mt1 < 25);
        if (!v0) break;

        // lane A-row base (padded coords) per tile
        int pr0, pr1;
        {
            int m = mt0 * 16 + li + sel8 * 8;
            int my = m / 20;
            pr0 = my * 22 + (m - my * 20);
        }
        {
            int mm = (v1 ? mt1 : mt0) * 16 + li + sel8 * 8;
            int my = mm / 20;
            pr1 = my * 22 + (mm - my * 20);
        }

        float acc0[4][4], acc1[4][4];
#pragma unroll
        for (int j = 0; j < 4; j++)
#pragma unroll
            for (int k = 0; k < 4; k++) { acc0[j][k] = 0.f; acc1[j][k] = 0.f; }

#pragma unroll 1
        for (int tap = 0; tap < 9; tap++) {
            const int dyx = (tap / 3) * 22 + (tap % 3);
#pragma unroll
            for (int kc = 0; kc < 2; kc++) {
                // ---- B fragments: once per (tap,kc), shared by both tiles ----
                const uint32_t brow = wb
                    + (uint32_t)(tap * 32 + kc * 16 + li + sel8 * 8) * HSTRIDE;
                const uint32_t cb_ = (uint32_t)selk * 16;
                uint32_t bf[8];
                ldm_x4_t(brow + cb_,       bf[0], bf[1], bf[2], bf[3]);
                ldm_x4_t(brow + cb_ + 32,  bf[4], bf[5], bf[6], bf[7]);

                const uint32_t ca = (uint32_t)(kc * 2 + selk) * 16;

                // ---- tile 0 ----
                {
                    const uint32_t arow = hb + (uint32_t)(pr0 + dyx) * HSTRIDE;
                    uint32_t a0, a1, a2, a3;
                    ldm_x4(arow + ca, a0, a1, a2, a3);
#pragma unroll
                    for (int j = 0; j < 4; j++)
                        mma16816(acc0[j], a0, a1, a2, a3, bf[2 * j], bf[2 * j + 1]);
                }
                // ---- tile 1 ----
                if (v1) {
                    const uint32_t arow = hb + (uint32_t)(pr1 + dyx) * HSTRIDE;
                    uint32_t a0, a1, a2, a3;
                    ldm_x4(arow + ca, a0, a1, a2, a3);
#pragma unroll
                    for (int j = 0; j < 4; j++)
                        mma16816(acc1[j], a0, a1, a2, a3, bf[2 * j], bf[2 * j + 1]);
                }
            }
        }

        // ---- epilogue for this pass ----
#pragma unroll 1
        for (int tt = 0; tt < 2; tt++) {
            if (tt == 1 && !v1) break;
            const int m0 = (tt == 0 ? mt0 : mt1) * 16;
            const int p0 = m0 + g;
            const int p1 = p0 + 8;
            const int y0 = p0 / 20, x0 = p0 - y0 * 20;
            const int y1 = p1 / 20, x1 = p1 - y1 * 20;
            const size_t pa0 = (size_t)(gtile + y0 * W_ + x0);
            const size_t pa1 = (size_t)(gtile + y1 * W_ + x1);
            float (*ac)[4] = (tt == 0) ? acc0 : acc1;
#pragma unroll
            for (int j = 0; j < 4; j++) {
                const int oc = j * 8 + 2 * tg;
                const size_t a00 = bb + (size_t)oc * HW + pa0;
                const size_t a10 = bb + (size_t)oc * HW + pa1;
                out[a00]      = ac[j][0] + cb0[j] + x[a00];
                out[a00 + HW] = ac[j][1] + cb1[j] + x[a00 + HW];
                out[a10]      = ac[j][2] + cb0[j] + x[a10];
                out[a10 + HW] = ac[j][3] + cb1[j] + x[a10 + HW];
            }
        }
    }
}

// ---------------------------------------------------------------------------
extern "C" void kernel_launch(void* const* d_in, const int* in_sizes, int n_in,
                              void* d_out, int out_size)
{
    const float* x      = (const float*)d_in[0];
    const float* gamma  = (const float*)d_in[1];
    const float* beta   = (const float*)d_in[2];
    const float* conv_w = (const float*)d_in[3];
    const float* conv_b = (const float*)d_in[4];
    float* out = (float*)d_out;

    bn_stats_kernel<<<NT * C_, 256>>>(x, gamma, beta, conv_w);

    cudaFuncSetAttribute(conv_kernel,
                         cudaFuncAttributeMaxDynamicSharedMemorySize, SMEM_REQ);
    conv_kernel<<<NT * B_, NTHREADS, SMEM_REQ>>>(x, conv_b, out);
}

// round 13
// speedup vs baseline: 3.1600x; 1.1114x over previous
#include <cuda_runtime.h>
#include <cuda_fp16.h>
#include <cstdint>

#define B_  32
#define C_  32
#define H_  160
#define W_  160
#define TH  20
#define TW  20
#define NT  64
#define EPS 1e-5f
#define HW  (H_ * W_)        // 25600

#define NTHREADS 416         // 13 warps: 13 x T=2 = 26 m-tiles (25 real + 1 dummy)

// H tile: 484 rows (22x22 padded pixels), 80B stride (64B content: 32ch fp16)
#define HSTRIDE 80
#define H_BYTES (484 * HSTRIDE)        // 38720
// Weights: 288 rows (tap*32+ic), 80B stride (32 oc fp16 = 64B content)
#define W_BYTES (288 * HSTRIDE)        // 23040
#define SMEM_REQ (1024 + H_BYTES + W_BYTES + 256)   // 63040

__device__ float d_scale[NT * C_];
__device__ float d_shift[NT * C_];
// fp16 weights: [row = tap*32+ic][32 oc fp16]
__device__ __align__(16) __half g_w2[NT][288 * 32];

__device__ __forceinline__ uint32_t smem_u32(const void* p) {
    uint32_t a;
    asm("{ .reg .u64 t; cvta.to.shared.u64 t, %1; cvt.u32.u64 %0, t; }" : "=r"(a) : "l"(p));
    return a;
}

__device__ __forceinline__ void ldm_x4(uint32_t addr,
                                       uint32_t& r0, uint32_t& r1,
                                       uint32_t& r2, uint32_t& r3) {
    asm volatile("ldmatrix.sync.aligned.m8n8.x4.shared.b16 {%0,%1,%2,%3}, [%4];"
                 : "=r"(r0), "=r"(r1), "=r"(r2), "=r"(r3) : "r"(addr));
}
__device__ __forceinline__ void ldm_x4_t(uint32_t addr,
                                         uint32_t& r0, uint32_t& r1,
                                         uint32_t& r2, uint32_t& r3) {
    asm volatile("ldmatrix.sync.aligned.m8n8.x4.trans.shared.b16 {%0,%1,%2,%3}, [%4];"
                 : "=r"(r0), "=r"(r1), "=r"(r2), "=r"(r3) : "r"(addr));
}
__device__ __forceinline__ void mma16816(float* d, uint32_t a0, uint32_t a1,
                                         uint32_t a2, uint32_t a3,
                                         uint32_t b0, uint32_t b1) {
    asm volatile(
        "mma.sync.aligned.m16n8k16.row.col.f32.f16.f16.f32 "
        "{%0,%1,%2,%3},{%4,%5,%6,%7},{%8,%9},{%0,%1,%2,%3};"
        : "+f"(d[0]), "+f"(d[1]), "+f"(d[2]), "+f"(d[3])
        : "r"(a0), "r"(a1), "r"(a2), "r"(a3), "r"(b0), "r"(b1));
}

// ---------------------------------------------------------------------------
// Kernel 1: BN stats per (tile, channel=oc) + fp16 weight pack into g_w2.
// ---------------------------------------------------------------------------
__global__ __launch_bounds__(256) void bn_stats_kernel(
    const float* __restrict__ x,
    const float* __restrict__ gamma,
    const float* __restrict__ beta,
    const float* __restrict__ conv_w)
{
    const int bid = blockIdx.x;           // t*32 + c
    const int t = bid >> 5;
    const int c = bid & 31;
    const int ti = t >> 3, tj = t & 7;

    const float* base = x + (size_t)c * HW + (size_t)(ti * TH) * W_ + tj * TW;
    const size_t bstride = (size_t)C_ * HW;

    float s = 0.f, s2 = 0.f;
    for (int i = threadIdx.x; i < B_ * TH * 5; i += 256) {
        int b = i / (TH * 5);
        int r = i - b * (TH * 5);
        int y = r / 5, xq = r - y * 5;
        float4 v = *reinterpret_cast<const float4*>(
            &base[(size_t)b * bstride + y * W_ + xq * 4]);
        s  += (v.x + v.y) + (v.z + v.w);
        s2 += (v.x * v.x + v.y * v.y) + (v.z * v.z + v.w * v.w);
    }

    // weight pack for oc = c: row = tap*32 + ic
    for (int i = threadIdx.x; i < 288; i += 256) {
        int ic = i / 9, tap = i - ic * 9;
        float w = conv_w[(((size_t)t * C_ + c) * C_ + ic) * 9 + tap];
        g_w2[t][(tap * 32 + ic) * 32 + c] = __float2half(w);
    }

    __shared__ float ss[256], ss2[256];
    ss[threadIdx.x] = s;
    ss2[threadIdx.x] = s2;
    __syncthreads();
    for (int off = 128; off > 0; off >>= 1) {
        if (threadIdx.x < off) {
            ss[threadIdx.x]  += ss[threadIdx.x + off];
            ss2[threadIdx.x] += ss2[threadIdx.x + off];
        }
        __syncthreads();
    }
    if (threadIdx.x == 0) {
        const float invN = 1.f / (float)(B_ * TH * TW);
        float mean = ss[0] * invN;
        float var  = ss2[0] * invN - mean * mean;
        float sc = gamma[bid] * rsqrtf(var + EPS);
        d_scale[bid] = sc;
        d_shift[bid] = beta[bid] - mean * sc;
    }
}

// ---------------------------------------------------------------------------
// Kernel 2: per-(tile, batch) implicit-GEMM 3x3 conv via fp16 mma.sync.
// 416 threads = 13 warps, T=2 tiles each, single balanced pass (26 tiles,
// last tile is dummy work with stores suppressed).
// ---------------------------------------------------------------------------
__global__ __launch_bounds__(NTHREADS, 2) void conv_kernel(
    const float* __restrict__ x,
    const float* __restrict__ conv_b,
    float* __restrict__ out)
{
    extern __shared__ char smem[];
    const uint32_t sbase = smem_u32(smem);
    const uint32_t hb = (sbase + 1023u) & ~1023u;
    const uint32_t wb = hb + H_BYTES;
    char* hptr = smem + (hb - sbase);
    char* wptr = smem + (wb - sbase);
    float* sscale = reinterpret_cast<float*>(smem + (wb - sbase) + W_BYTES);
    float* sshift = sscale + 32;

    const int bid = blockIdx.x;     // t*32 + b
    const int t = bid >> 5;
    const int b = bid & 31;
    const int ti = t >> 3, tj = t & 7;
    const int tid = threadIdx.x;
    const int warp = tid >> 5;
    const int lane = tid & 31;

    // ---- stage BN params ----
    if (tid < 32) {
        sscale[tid] = d_scale[t * C_ + tid];
        sshift[tid] = d_shift[t * C_ + tid];
    }

    // ---- zero h region (halo must be 0) ----
    {
        uint4 z = make_uint4(0, 0, 0, 0);
        uint4* hz = reinterpret_cast<uint4*>(hptr);
        for (int i = tid; i < H_BYTES / 16; i += NTHREADS) hz[i] = z;
    }

    // ---- copy fp16 weights: 288 rows x 64B content (2 x 32B chunks) ----
    {
        const uint4* gsrc = reinterpret_cast<const uint4*>(g_w2[t]);
        uint4* wdst = reinterpret_cast<uint4*>(wptr);
        for (int i = tid; i < 288 * 2; i += NTHREADS) {
            int row = i >> 1, hf = i & 1;
            wdst[(row * HSTRIDE + hf * 32) >> 4]       = gsrc[(row * 64 + hf * 32) >> 4];
            wdst[((row * HSTRIDE + hf * 32) >> 4) + 1] = gsrc[((row * 64 + hf * 32) >> 4) + 1];
        }
    }
    __syncthreads();

    // ---- prologue: thread = 4 channels x 1 pixel -> one STS.64 ----
    const size_t xtile = ((size_t)b * C_) * HW + (size_t)(ti * TH) * W_ + tj * TW;
    for (int i = tid; i < 8 * TH * TW; i += NTHREADS) {   // 3200 work items
        int p  = i % 400;          // pixel
        int cq = i / 400;          // channel quad
        int py = p / 20, px = p - py * 20;
        int c0 = cq * 4;
        const float* xp = &x[xtile + (size_t)c0 * HW + py * W_ + px];
        uint32_t hrow = (uint32_t)((py + 1) * 22 + px + 1) * HSTRIDE;
        __half hq[4];
#pragma unroll
        for (int j = 0; j < 4; j++) {
            float f = fmaxf(fmaf(xp[(size_t)j * HW], sscale[c0 + j], sshift[c0 + j]), 0.f);
            hq[j] = __float2half(f);
        }
        *reinterpret_cast<uint64_t*>(hptr + hrow + cq * 8) = *reinterpret_cast<uint64_t*>(hq);
    }
    __syncthreads();

    // ---- warp-level implicit GEMM: warp w owns tiles {2w, 2w+1}, balanced ----
    const int li   = lane & 7;
    const int sel8 = (lane >> 3) & 1;
    const int selk = (lane >> 4) & 1;
    const int tg   = lane & 3;
    const int g    = lane >> 2;

    float cb0[4], cb1[4];
#pragma unroll
    for (int j = 0; j < 4; j++) {
        cb0[j] = conv_b[t * C_ + j * 8 + 2 * tg];
        cb1[j] = conv_b[t * C_ + j * 8 + 2 * tg + 1];
    }

    const size_t bb = (size_t)b * C_ * HW;
    const int gtile = (ti * TH) * W_ + tj * TW;

    const int mt0 = 2 * warp;
    const int mt1 = mt0 + 1;

    // lane A-row base (padded coords) per tile; clamp dummy tile 25 into range
    int pr0, pr1;
    {
        int m = mt0 * 16 + li + sel8 * 8;        // <= 399 always (mt0 <= 24)
        int my = m / 20;
        pr0 = my * 22 + (m - my * 20);
    }
    {
        int mm = mt1 * 16 + li + sel8 * 8;
        if (mm > 399) mm = 399;                  // tile 25: dummy, reads clamped
        int my = mm / 20;
        pr1 = my * 22 + (mm - my * 20);
    }

    float acc0[4][4], acc1[4][4];
#pragma unroll
    for (int j = 0; j < 4; j++)
#pragma unroll
        for (int k = 0; k < 4; k++) { acc0[j][k] = 0.f; acc1[j][k] = 0.f; }

#pragma unroll 1
    for (int tap = 0; tap < 9; tap++) {
        const int dyx = (tap / 3) * 22 + (tap % 3);
#pragma unroll
        for (int kc = 0; kc < 2; kc++) {
            // ---- B fragments: once per (tap,kc), shared by both tiles ----
            const uint32_t brow = wb
                + (uint32_t)(tap * 32 + kc * 16 + li + sel8 * 8) * HSTRIDE;
            const uint32_t cb_ = (uint32_t)selk * 16;
            uint32_t bf[8];
            ldm_x4_t(brow + cb_,       bf[0], bf[1], bf[2], bf[3]);
            ldm_x4_t(brow + cb_ + 32,  bf[4], bf[5], bf[6], bf[7]);

            const uint32_t ca = (uint32_t)(kc * 2 + selk) * 16;

            // ---- tile 0 ----
            {
                const uint32_t arow = hb + (uint32_t)(pr0 + dyx) * HSTRIDE;
                uint32_t a0, a1, a2, a3;
                ldm_x4(arow + ca, a0, a1, a2, a3);
#pragma unroll
                for (int j = 0; j < 4; j++)
                    mma16816(acc0[j], a0, a1, a2, a3, bf[2 * j], bf[2 * j + 1]);
            }
            // ---- tile 1 ----
            {
                const uint32_t arow = hb + (uint32_t)(pr1 + dyx) * HSTRIDE;
                uint32_t a0, a1, a2, a3;
                ldm_x4(arow + ca, a0, a1, a2, a3);
#pragma unroll
                for (int j = 0; j < 4; j++)
                    mma16816(acc1[j], a0, a1, a2, a3, bf[2 * j], bf[2 * j + 1]);
            }
        }
    }

    // ---- epilogue: + bias + residual (skip dummy tile 25) ----
#pragma unroll 1
    for (int tt = 0; tt < 2; tt++) {
        const int mt = (tt == 0) ? mt0 : mt1;
        const int m0 = mt * 16;
        if (m0 >= 400) break;                    // dummy tile: no stores
        const int p0 = m0 + g;
        const int p1 = p0 + 8;
        const int y0 = p0 / 20, x0 = p0 - y0 * 20;
        const int y1 = p1 / 20, x1 = p1 - y1 * 20;
        const size_t pa0 = (size_t)(gtile + y0 * W_ + x0);
        const size_t pa1 = (size_t)(gtile + y1 * W_ + x1);
        float (*ac)[4] = (tt == 0) ? acc0 : acc1;
#pragma unroll
        for (int j = 0; j < 4; j++) {
            const int oc = j * 8 + 2 * tg;
            const size_t a00 = bb + (size_t)oc * HW + pa0;
            const size_t a10 = bb + (size_t)oc * HW + pa1;
            out[a00]      = ac[j][0] + cb0[j] + x[a00];
            out[a00 + HW] = ac[j][1] + cb1[j] + x[a00 + HW];
            out[a10]      = ac[j][2] + cb0[j] + x[a10];
            out[a10 + HW] = ac[j][3] + cb1[j] + x[a10 + HW];
        }
    }
}

// ---------------------------------------------------------------------------
extern "C" void kernel_launch(void* const* d_in, const int* in_sizes, int n_in,
                              void* d_out, int out_size)
{
    const float* x      = (const float*)d_in[0];
    const float* gamma  = (const float*)d_in[1];
    const float* beta   = (const float*)d_in[2];
    const float* conv_w = (const float*)d_in[3];
    const float* conv_b = (const float*)d_in[4];
    float* out = (float*)d_out;

    bn_stats_kernel<<<NT * C_, 256>>>(x, gamma, beta, conv_w);

    cudaFuncSetAttribute(conv_kernel,
                         cudaFuncAttributeMaxDynamicSharedMemorySize, SMEM_REQ);
    conv_kernel<<<NT * B_, NTHREADS, SMEM_REQ>>>(x, conv_b, out);
}